// round 3
// baseline (speedup 1.0000x reference)
#include <cuda_runtime.h>

// KinematicDOFs — R3:
//  K1: backbone block scans + fused last-block seed scan (2 launches total)
//  K3: 4 lanes x 4 items per chain, MUFU trig, register-cached bond hts

#define B_CHAIN 16384
#define S_SIDE  15

#define TPB1    128
#define NBLK1   (B_CHAIN / TPB1)     // 128
#define LOG_TPB1_SHIFT 7

#define TPB3    256
#define NBLK3   ((B_CHAIN * 4) / TPB3)   // 256

__device__ float g_local[12 * B_CHAIN];  // SoA
__device__ float g_agg[NBLK1 * 12];
__device__ float g_seed[NBLK1 * 12];
__device__ int   g_count = 0;            // self-resetting last-block counter

__device__ __forceinline__ void affmul(const float* a, const float* b, float* c)
{
#pragma unroll
    for (int i = 0; i < 3; ++i) {
        float a0 = a[i*4+0], a1 = a[i*4+1], a2 = a[i*4+2], a3 = a[i*4+3];
        c[i*4+0] = a0*b[0] + a1*b[4] + a2*b[8];
        c[i*4+1] = a0*b[1] + a1*b[5] + a2*b[9];
        c[i*4+2] = a0*b[2] + a1*b[6] + a2*b[10];
        c[i*4+3] = a0*b[3] + a1*b[7] + a2*b[11] + a3;
    }
}

// accurate version (backbone — errors compound over 16384 products)
__device__ __forceinline__ void bond_ht_acc(float a, float b, float d, float c, float* m)
{
    float sa, ca, sb, cb, sc, cc;
    sincosf(a, &sa, &ca);
    sincosf(b, &sb, &cb);
    sincosf(c, &sc, &cc);
    m[0] = cb;      m[1] = -sb*cc;            m[2] =  sb*sc;            m[3]  = d*cb;
    m[4] = ca*sb;   m[5] = ca*cb*cc - sa*sc;  m[6] = -ca*cb*sc - sa*cc; m[7] = ca*d*sb;
    m[8] = sa*sb;   m[9] = sa*cb*cc + ca*sc;  m[10]= -sa*cb*sc + ca*cc; m[11]= sa*d*sb;
}

// fast MUFU version (side chains — only 15 deep)
__device__ __forceinline__ void bond_ht_fast(float a, float b, float d, float c, float* m)
{
    float sa = __sinf(a), ca = __cosf(a);
    float sb = __sinf(b), cb = __cosf(b);
    float sc = __sinf(c), cc = __cosf(c);
    m[0] = cb;      m[1] = -sb*cc;            m[2] =  sb*sc;            m[3]  = d*cb;
    m[4] = ca*sb;   m[5] = ca*cb*cc - sa*sc;  m[6] = -ca*cb*sc - sa*cc; m[7] = ca*d*sb;
    m[8] = sa*sb;   m[9] = sa*cb*cc + ca*sc;  m[10]= -sa*cb*sc + ca*cc; m[11]= sa*d*sb;
}

__device__ __forceinline__ void make_ht(int dt, float4 d, float* m)
{
    if (dt == 2) {
        bond_ht_acc(d.x, d.y, d.z, d.w, m);
    } else if (dt == 1) {
        float s3, c3; sincosf(d.w, &s3, &c3);
        m[0]=1.f; m[1]=0.f; m[2]=0.f;  m[3]=d.x;
        m[4]=0.f; m[5]=c3;  m[6]=-s3;  m[7]=d.y;
        m[8]=0.f; m[9]=s3;  m[10]=c3;  m[11]=d.z;
    } else {
        m[0]=1.f; m[1]=0.f; m[2]=0.f;  m[3]=0.f;
        m[4]=0.f; m[5]=1.f; m[6]=0.f;  m[7]=0.f;
        m[8]=0.f; m[9]=0.f; m[10]=1.f; m[11]=0.f;
    }
}

// scan NBLK1(=128) block aggregates -> exclusive seeds (run by 128 threads)
__device__ void seed_scan(int t)
{
    const int lane = t & 31;
    const int w    = t >> 5;

    float a[12];
#pragma unroll
    for (int k = 0; k < 12; ++k) a[k] = g_agg[t * 12 + k];

#pragma unroll
    for (int dlt = 1; dlt < 32; dlt <<= 1) {
        float o[12];
#pragma unroll
        for (int k = 0; k < 12; ++k) o[k] = __shfl_up_sync(0xffffffffu, a[k], dlt);
        if (lane >= dlt) {
            float tm[12]; affmul(o, a, tm);
#pragma unroll
            for (int k = 0; k < 12; ++k) a[k] = tm[k];
        }
    }

    __shared__ float s_wagg[4][12];
    __shared__ float s_wincl[4][12];
    __shared__ float s_incl[128][12];
    if (lane == 31) {
#pragma unroll
        for (int k = 0; k < 12; ++k) s_wagg[w][k] = a[k];
    }
    __syncthreads();

    if (w == 0) {
        int src = lane < 4 ? lane : 3;
        float b[12];
#pragma unroll
        for (int k = 0; k < 12; ++k) b[k] = s_wagg[src][k];
#pragma unroll
        for (int dlt = 1; dlt < 4; dlt <<= 1) {
            float o[12];
#pragma unroll
            for (int k = 0; k < 12; ++k) o[k] = __shfl_up_sync(0xffffffffu, b[k], dlt);
            if (lane >= dlt && lane < 4) {
                float tm[12]; affmul(o, b, tm);
#pragma unroll
                for (int k = 0; k < 12; ++k) b[k] = tm[k];
            }
        }
        if (lane < 4) {
#pragma unroll
            for (int k = 0; k < 12; ++k) s_wincl[lane][k] = b[k];
        }
    }
    __syncthreads();

    if (w > 0) {
        float sd[12], tm[12];
#pragma unroll
        for (int k = 0; k < 12; ++k) sd[k] = s_wincl[w - 1][k];
        affmul(sd, a, tm);
#pragma unroll
        for (int k = 0; k < 12; ++k) a[k] = tm[k];
    }
#pragma unroll
    for (int k = 0; k < 12; ++k) s_incl[t][k] = a[k];
    __syncthreads();

    float sd[12];
    if (t == 0) {
        sd[0]=1.f; sd[1]=0.f; sd[2]=0.f;  sd[3]=0.f;
        sd[4]=0.f; sd[5]=1.f; sd[6]=0.f;  sd[7]=0.f;
        sd[8]=0.f; sd[9]=0.f; sd[10]=1.f; sd[11]=0.f;
    } else {
#pragma unroll
        for (int k = 0; k < 12; ++k) sd[k] = s_incl[t - 1][k];
    }
#pragma unroll
    for (int k = 0; k < 12; ++k) g_seed[t * 12 + k] = sd[k];
}

// ---------------------------------------------------------------------------
// K1: per-block inclusive scan of backbone + fused final seed scan
// ---------------------------------------------------------------------------
__global__ void __launch_bounds__(TPB1)
k_scan1(const float* __restrict__ dofs, const int* __restrict__ doftype)
{
    const int e    = blockIdx.x * TPB1 + threadIdx.x;
    const int atom = e + 1;
    const int lane = threadIdx.x & 31;
    const int warp = threadIdx.x >> 5;

    float4 d = reinterpret_cast<const float4*>(dofs)[e];
    float m[12];
    make_ht(doftype[atom], d, m);

#pragma unroll
    for (int dlt = 1; dlt < 32; dlt <<= 1) {
        float o[12];
#pragma unroll
        for (int k = 0; k < 12; ++k) o[k] = __shfl_up_sync(0xffffffffu, m[k], dlt);
        if (lane >= dlt) {
            float t[12]; affmul(o, m, t);
#pragma unroll
            for (int k = 0; k < 12; ++k) m[k] = t[k];
        }
    }

    __shared__ float s_agg[4][12];
    __shared__ float s_incl[4][12];
    if (lane == 31) {
#pragma unroll
        for (int k = 0; k < 12; ++k) s_agg[warp][k] = m[k];
    }
    __syncthreads();

    if (warp == 0) {
        int src = lane < 4 ? lane : 3;
        float a[12];
#pragma unroll
        for (int k = 0; k < 12; ++k) a[k] = s_agg[src][k];
#pragma unroll
        for (int dlt = 1; dlt < 4; dlt <<= 1) {
            float o[12];
#pragma unroll
            for (int k = 0; k < 12; ++k) o[k] = __shfl_up_sync(0xffffffffu, a[k], dlt);
            if (lane >= dlt && lane < 4) {
                float t[12]; affmul(o, a, t);
#pragma unroll
                for (int k = 0; k < 12; ++k) a[k] = t[k];
            }
        }
        if (lane < 4) {
#pragma unroll
            for (int k = 0; k < 12; ++k) s_incl[lane][k] = a[k];
        }
    }
    __syncthreads();

    if (warp > 0) {
        float sd[12], t[12];
#pragma unroll
        for (int k = 0; k < 12; ++k) sd[k] = s_incl[warp - 1][k];
        affmul(sd, m, t);
#pragma unroll
        for (int k = 0; k < 12; ++k) m[k] = t[k];
    }

#pragma unroll
    for (int k = 0; k < 12; ++k) g_local[k * B_CHAIN + e] = m[k];

    if (threadIdx.x == TPB1 - 1) {
#pragma unroll
        for (int k = 0; k < 12; ++k) g_agg[blockIdx.x * 12 + k] = m[k];
    }

    // last block to finish performs the seed scan (K2 fused)
    __shared__ int s_last;
    __threadfence();
    __syncthreads();
    if (threadIdx.x == 0) {
        int c = atomicAdd(&g_count, 1);
        s_last = (c == NBLK1 - 1) ? 1 : 0;
    }
    __syncthreads();
    if (s_last) {
        seed_scan(threadIdx.x);
        if (threadIdx.x == 0) g_count = 0;   // reset for next graph replay
    }
}

// ---------------------------------------------------------------------------
// K3: 4 lanes per chain, 4 items per lane (item 0 = parent global).
// ---------------------------------------------------------------------------
__global__ void __launch_bounds__(TPB3)
k_chains(const float* __restrict__ dofs,
         const int*   __restrict__ kin_id,
         float*       __restrict__ out)
{
    const int tid   = blockIdx.x * TPB3 + threadIdx.x;
    const int chain = tid >> 2;          // 0..16383
    const int r     = tid & 3;           // lane within chain (4 items each)

    // compute this lane's 4 item transforms into registers
    float h[4][12];
    int atom0;                           // first atom handled by this lane
    if (r == 0) {
        // item 0: parent global = seed o local
        atom0 = chain + 1;
        const int e = chain;
        const int b = e >> LOG_TPB1_SHIFT;
        float loc[12], sd[12];
#pragma unroll
        for (int k = 0; k < 12; ++k) loc[k] = g_local[k * B_CHAIN + e];
#pragma unroll
        for (int k = 0; k < 12; ++k) sd[k] = g_seed[b * 12 + k];
        affmul(sd, loc, h[0]);
#pragma unroll
        for (int j = 1; j < 4; ++j) {
            int a = 1 + B_CHAIN + chain * S_SIDE + (j - 1);
            float4 dd = reinterpret_cast<const float4*>(dofs)[a - 1];
            bond_ht_fast(dd.x, dd.y, dd.z, dd.w, h[j]);
        }
    } else {
        atom0 = 1 + B_CHAIN + chain * S_SIDE + (4 * r - 1);
#pragma unroll
        for (int j = 0; j < 4; ++j) {
            float4 dd = reinterpret_cast<const float4*>(dofs)[atom0 + j - 1];
            bond_ht_fast(dd.x, dd.y, dd.z, dd.w, h[j]);
        }
    }

    // lane product P = h0 o h1 o h2 o h3
    float P[12], T[12];
    affmul(h[0], h[1], P);
    affmul(P, h[2], T);
    affmul(T, h[3], P);

    // inclusive scan of P over the 4 lanes of this chain (2 rounds)
#pragma unroll
    for (int dlt = 1; dlt < 4; dlt <<= 1) {
        float o[12];
#pragma unroll
        for (int k = 0; k < 12; ++k) o[k] = __shfl_up_sync(0xffffffffu, P[k], dlt);
        if (r >= dlt) {
            float t[12]; affmul(o, P, t);
#pragma unroll
            for (int k = 0; k < 12; ++k) P[k] = t[k];
        }
    }

    // exclusive seed for this lane
    float S[12];
    {
        float o[12];
#pragma unroll
        for (int k = 0; k < 12; ++k) o[k] = __shfl_up_sync(0xffffffffu, P[k], 1);
        if (r == 0) {
            S[0]=1.f; S[1]=0.f; S[2]=0.f;  S[3]=0.f;
            S[4]=0.f; S[5]=1.f; S[6]=0.f;  S[7]=0.f;
            S[8]=0.f; S[9]=0.f; S[10]=1.f; S[11]=0.f;
        } else {
#pragma unroll
            for (int k = 0; k < 12; ++k) S[k] = o[k];
        }
    }

    // emit the 4 items: M = S o h0 ... ; atoms handled by this lane are
    // atom0, atom0+1, atom0+2, atom0+3 (contiguous for r>0; for r==0 item 0
    // is the parent atom and items 1..3 are the first three side atoms).
    float M[12];
    affmul(S, h[0], M);
    {
        int kid = kin_id[atom0];
        out[kid * 3 + 0] = M[3];
        out[kid * 3 + 1] = M[7];
        out[kid * 3 + 2] = M[11];
    }
#pragma unroll
    for (int j = 1; j < 4; ++j) {
        float t[12];
        affmul(M, h[j], t);
#pragma unroll
        for (int k = 0; k < 12; ++k) M[k] = t[k];
        int a;
        if (r == 0)
            a = 1 + B_CHAIN + chain * S_SIDE + (j - 1);
        else
            a = atom0 + j;
        int kid = kin_id[a];
        out[kid * 3 + 0] = M[3];
        out[kid * 3 + 1] = M[7];
        out[kid * 3 + 2] = M[11];
    }
}

extern "C" void kernel_launch(void* const* d_in, const int* in_sizes, int n_in,
                              void* d_out, int out_size)
{
    const float* dofs    = (const float*)d_in[0];
    const int*   doftype = (const int*)  d_in[4];
    const int*   kin_id  = (const int*)  d_in[8];
    float*       out     = (float*)d_out;

    k_scan1<<<NBLK1, TPB1>>>(dofs, doftype);
    k_chains<<<NBLK3, TPB3>>>(dofs, kin_id, out);
}